// round 15
// baseline (speedup 1.0000x reference)
#include <cuda_runtime.h>
#include <cuda_fp16.h>
#include <cstdint>
#include <cstddef>

// ---------------------------------------------------------------------------
// Problem constants
// ---------------------------------------------------------------------------
#define TOKENS   8192
#define IN_F     4096
#define OUT_F    4096
#define GS       128

// GEMM tiling (fp16): BK = 64 halves = 128B rows
#define BM 128
#define BN 128
#define BK 64
#define STAGES 3                      // 96KB smem -> 2 CTAs/SM
#define NCHUNK (IN_F / BK)            // 64
#define GRID_N (OUT_F / BN)           // 32
#define GRID_M (TOKENS / BM)          // 64

#define OFF_B       (BM * BK * 2)     // 16384 (A tile bytes)
#define STAGE_BYTES ((BM + BN) * BK * 2)   // 32768
#define GEMM_SMEM   (STAGES * STAGE_BYTES) // 98304

// ---------------------------------------------------------------------------
// Device scratch (static -- no cudaMalloc anywhere)
// ---------------------------------------------------------------------------
__device__ __half g_x[(size_t)TOKENS * IN_F];   // x rounded to fp16
__device__ __half g_w[(size_t)OUT_F * IN_F];    // dequant + perm-folded fp16

// ---------------------------------------------------------------------------
// PTX helpers (family-common: mma.sync / ldmatrix / cp.async)
// ---------------------------------------------------------------------------
__device__ __forceinline__ uint32_t smem_u32(const void* p) {
    uint32_t a;
    asm("{ .reg .u64 t; cvta.to.shared.u64 t, %1; cvt.u32.u64 %0, t; }"
        : "=r"(a) : "l"(p));
    return a;
}

__device__ __forceinline__ void cp_async16(uint32_t smem_addr, const void* gptr) {
    asm volatile("cp.async.cg.shared.global [%0], [%1], 16;"
                 :: "r"(smem_addr),
                    "l"((unsigned long long)__cvta_generic_to_global(gptr))
                 : "memory");
}
#define CP_COMMIT() asm volatile("cp.async.commit_group;" ::: "memory")
#define CP_WAIT(n)  asm volatile("cp.async.wait_group %0;" :: "n"(n) : "memory")

#define LDSM4(r, addr)                                                         \
    asm volatile("ldmatrix.sync.aligned.m8n8.x4.shared.b16 {%0,%1,%2,%3}, [%4];" \
                 : "=r"((r)[0]), "=r"((r)[1]), "=r"((r)[2]), "=r"((r)[3])      \
                 : "r"(addr))

// m16n8k16 fp16 MMA, fp32 accumulate.
#define MMA_F16(d, a, b0, b1)                                                  \
    asm volatile(                                                              \
        "mma.sync.aligned.m16n8k16.row.col.f32.f16.f16.f32 "                   \
        "{%0,%1,%2,%3}, {%4,%5,%6,%7}, {%8,%9}, {%0,%1,%2,%3};"                \
        : "+f"((d)[0]), "+f"((d)[1]), "+f"((d)[2]), "+f"((d)[3])               \
        : "r"((a)[0]), "r"((a)[1]), "r"((a)[2]), "r"((a)[3]),                  \
          "r"(b0), "r"(b1))

// ---------------------------------------------------------------------------
// ONE fused prep kernel. W blocks build the inverse permutation locally in
// smem (scatter sinv[perm[j]] = j), so no separate inv_perm kernel or global
// g_inv array is needed.
// Blocks [0, OUT_F): dequant + perm-fold one W row (gather via sinv).
// Blocks [OUT_F, OUT_F+XBLOCKS): convert a 1024-float4 slab of x to fp16.
// ---------------------------------------------------------------------------
#define XBLOCKS (TOKENS * IN_F / 4 / 1024)       // 8192

__global__ void __launch_bounds__(256)
prep_kernel(const float4* __restrict__ x, const int* __restrict__ wp,
            const float* __restrict__ ws, const int* __restrict__ perm) {
    const int bid = blockIdx.x;
    const int tid = threadIdx.x;
    if (bid < OUT_F) {
        // --- W path: inverse-perm in smem + dequant + perm-fold, fp16 ---
        __shared__ int   sinv[IN_F];             // 16KB
        __shared__ int   srow[IN_F / 2];         // 8KB
        __shared__ float sscale[IN_F / GS];      // 128B
        for (int j = tid; j < IN_F; j += 256) sinv[perm[j]] = j;
        for (int i = tid; i < IN_F / 2; i += 256)
            srow[i] = wp[(size_t)bid * (IN_F / 2) + i];
        if (tid < IN_F / GS) sscale[tid] = ws[(size_t)bid * (IN_F / GS) + tid];
        __syncthreads();
        for (int k = tid; k < IN_F; k += 256) {
            int j = sinv[k];                     // source (pre-perm) column
            int b = srow[j >> 1];
            int q = (((j & 1) ? (b >> 4) : b) & 0xF) - 8;
            float w = (float)q * sscale[j >> 7]; // group = j / 128
            g_w[(size_t)bid * IN_F + k] = __float2half_rn(w);
        }
    } else {
        // --- x path: fp32 -> fp16, 4 float4 per thread ---
        const int xb = bid - OUT_F;              // 0..XBLOCKS-1
        const float4* src = x + (size_t)xb * 1024;
        uint2* dst = reinterpret_cast<uint2*>(g_x) + (size_t)xb * 1024;
        #pragma unroll
        for (int it = 0; it < 4; ++it) {
            int i = tid + it * 256;
            float4 v = src[i];
            __half2 h0 = __floats2half2_rn(v.x, v.y);
            __half2 h1 = __floats2half2_rn(v.z, v.w);
            uint2 packed;
            packed.x = *reinterpret_cast<uint32_t*>(&h0);
            packed.y = *reinterpret_cast<uint32_t*>(&h1);
            dst[i] = packed;
        }
    }
}

// ---------------------------------------------------------------------------
// GEMM (R13/R14 version, measured 582.0us -- DO NOT TOUCH): 128x128 CTA tile,
// 3-stage cp.async pipeline, m16n8k16 fp16 MMA, ldmatrix.x4 fragment loads;
// refill split into two halves (post-barrier and mid-chunk). Warp grid
// 4(M) x 2(N); warp tile 32x64. 2 CTAs/SM.
// smem rows 128B; swizzle: (seg*16) ^ ((row&7)<<4).
// ---------------------------------------------------------------------------
__device__ __forceinline__ void load_stage_half(uint32_t sbase, int s, int chunk,
                                                int m0, int n0, int tid, int half) {
    uint32_t st = sbase + (uint32_t)s * STAGE_BYTES;
    const __half* gA = g_x + (size_t)m0 * IN_F + chunk * BK;
    const __half* gB = g_w + (size_t)n0 * IN_F + chunk * BK;
    #pragma unroll
    for (int it = half * 2; it < half * 2 + 2; ++it) {
        int u = tid + it * 256;                  // 0..1023
        int r = u >> 3, seg = u & 7;             // row, 16B-seg within 128B row
        uint32_t so = (uint32_t)(r * 128) + (uint32_t)((seg * 16) ^ ((r & 7) << 4));
        cp_async16(st + so,         gA + (size_t)r * IN_F + seg * 8);
        cp_async16(st + OFF_B + so, gB + (size_t)r * IN_F + seg * 8);
    }
}

__global__ void __launch_bounds__(256, 2)
gemm_kernel(const float* __restrict__ bias, float* __restrict__ out) {
    extern __shared__ char smem[];
    const uint32_t sbase = smem_u32(smem);
    const int tid  = threadIdx.x;
    const int wid  = tid >> 5;
    const int lane = tid & 31;
    const int bid  = blockIdx.x;
    const int n0 = (bid & (GRID_N - 1)) * BN;    // n-fast: W slab stays in L2
    const int m0 = (bid / GRID_N) * BM;

    const int wm = wid >> 1;                     // 0..3
    const int wn = wid & 1;                      // 0..1
    const int g  = lane >> 2;                    // 0..7
    const int t  = lane & 3;                     // 0..3

    // ldmatrix lane roles
    const int mtx = lane >> 3;                   // matrix index 0..3
    const int rr  = lane & 7;                    // row within matrix
    const uint32_t swz = (uint32_t)rr << 4;      // XOR swizzle for this row

    // A: matrix m -> rows (wm*32 + mi*16 + (m&1)*8 + rr), k-half (m>>1)
    const uint32_t aRowOff = (uint32_t)((wm * 32 + (mtx & 1) * 8 + rr) * 128);
    const uint32_t kbA = (uint32_t)((mtx >> 1) * 16);
    // B: matrix m -> rows (wn*64 + jp*16 + (m>>1)*8 + rr), k-half (m&1)
    const uint32_t bRowOff = (uint32_t)((wn * 64 + (mtx >> 1) * 8 + rr) * 128) + OFF_B;
    const uint32_t kbB = (uint32_t)((mtx & 1) * 16);

    float acc[2][8][4];
    #pragma unroll
    for (int i = 0; i < 2; ++i)
        #pragma unroll
        for (int j = 0; j < 8; ++j)
            #pragma unroll
            for (int c = 0; c < 4; ++c) acc[i][j][c] = 0.0f;

    #pragma unroll
    for (int c = 0; c < STAGES - 1; ++c) {
        load_stage_half(sbase, c, c, m0, n0, tid, 0);
        load_stage_half(sbase, c, c, m0, n0, tid, 1);
        CP_COMMIT();
    }

    int s_cons = 0, s_prod = STAGES - 1;

    #pragma unroll 1
    for (int i = 0; i < NCHUNK; ++i) {
        CP_WAIT(STAGES - 2);                     // chunk i resident
        __syncthreads();
        const bool refill = (i + STAGES - 1 < NCHUNK);
        if (refill) load_stage_half(sbase, s_prod, i + STAGES - 1, m0, n0, tid, 0);

        const uint32_t st = sbase + (uint32_t)s_cons * STAGE_BYTES;
        if (++s_cons == STAGES) s_cons = 0;

        #pragma unroll
        for (int ks = 0; ks < 4; ++ks) {         // k16 steps; 32B per step
            if (ks == 2) {                       // second refill half + commit
                if (refill) {
                    load_stage_half(sbase, s_prod, i + STAGES - 1, m0, n0, tid, 1);
                    if (++s_prod == STAGES) s_prod = 0;
                }
                CP_COMMIT();
            }
            const uint32_t colA = ((uint32_t)(ks * 32) + kbA) ^ swz;
            const uint32_t colB = ((uint32_t)(ks * 32) + kbB) ^ swz;
            uint32_t ar[2][4];
            LDSM4(ar[0], st + aRowOff + colA);              // mi=0 (rows +0)
            LDSM4(ar[1], st + aRowOff + 16 * 128 + colA);   // mi=1 (rows +16)
            #pragma unroll
            for (int jp = 0; jp < 4; ++jp) {     // regs 0,1 = j even; 2,3 = j odd
                uint32_t bq[4];
                LDSM4(bq, st + bRowOff + (uint32_t)(jp * 16 * 128) + colB);
                MMA_F16(acc[0][jp * 2],     ar[0], bq[0], bq[1]);
                MMA_F16(acc[1][jp * 2],     ar[1], bq[0], bq[1]);
                MMA_F16(acc[0][jp * 2 + 1], ar[0], bq[2], bq[3]);
                MMA_F16(acc[1][jp * 2 + 1], ar[1], bq[2], bq[3]);
            }
        }
    }

    // Epilogue: c0/c1 at (row, 2t), c2/c3 at (row+8, 2t); add bias, float2 stores
    #pragma unroll
    for (int mi = 0; mi < 2; ++mi) {
        const int row0 = m0 + wm * 32 + mi * 16 + g;
        #pragma unroll
        for (int j = 0; j < 8; ++j) {
            const int col = n0 + wn * 64 + j * 8 + t * 2;
            const float2 b2 = *reinterpret_cast<const float2*>(bias + col);
            float2 v0, v1;
            v0.x = acc[mi][j][0] + b2.x;  v0.y = acc[mi][j][1] + b2.y;
            v1.x = acc[mi][j][2] + b2.x;  v1.y = acc[mi][j][3] + b2.y;
            *reinterpret_cast<float2*>(out + (size_t)row0 * OUT_F + col) = v0;
            *reinterpret_cast<float2*>(out + (size_t)(row0 + 8) * OUT_F + col) = v1;
        }
    }
}

// ---------------------------------------------------------------------------
// Launch
// ---------------------------------------------------------------------------
extern "C" void kernel_launch(void* const* d_in, const int* in_sizes, int n_in,
                              void* d_out, int out_size) {
    const float* x    = (const float*)d_in[0];
    const int*   wp   = (const int*)d_in[1];
    const float* ws   = (const float*)d_in[2];
    const int*   perm = (const int*)d_in[3];
    const float* bias = (const float*)d_in[4];
    float* out = (float*)d_out;

    prep_kernel<<<OUT_F + XBLOCKS, 256>>>((const float4*)x, wp, ws, perm);

    cudaFuncSetAttribute(gemm_kernel, cudaFuncAttributeMaxDynamicSharedMemorySize,
                         GEMM_SMEM);
    gemm_kernel<<<GRID_M * GRID_N, 256, GEMM_SMEM>>>(bias, out);
}

// round 16
// speedup vs baseline: 1.0120x; 1.0120x over previous
#include <cuda_runtime.h>
#include <cuda_fp16.h>
#include <cstdint>
#include <cstddef>

// ---------------------------------------------------------------------------
// Problem constants
// ---------------------------------------------------------------------------
#define TOKENS   8192
#define IN_F     4096
#define OUT_F    4096
#define GS       128

// GEMM tiling (fp16): BK = 64 halves = 128B rows
#define BM 128
#define BN 128
#define BK 64
#define STAGES 3                      // 96KB smem -> 2 CTAs/SM
#define NCHUNK (IN_F / BK)            // 64
#define GRID_N (OUT_F / BN)           // 32
#define GRID_M (TOKENS / BM)          // 64

#define OFF_B       (BM * BK * 2)     // 16384 (A tile bytes)
#define STAGE_BYTES ((BM + BN) * BK * 2)   // 32768
#define GEMM_SMEM   (STAGES * STAGE_BYTES) // 98304

// ---------------------------------------------------------------------------
// Device scratch (static -- no cudaMalloc anywhere)
// ---------------------------------------------------------------------------
__device__ __half g_x[(size_t)TOKENS * IN_F];   // x rounded to fp16
__device__ __half g_w[(size_t)OUT_F * IN_F];    // dequant + perm-folded fp16
__device__ int    g_inv[IN_F];
__device__ int    g_inv_ready;                  // sticky flag (replay-benign)

// ---------------------------------------------------------------------------
// PTX helpers (family-common: mma.sync / ldmatrix / cp.async)
// ---------------------------------------------------------------------------
__device__ __forceinline__ uint32_t smem_u32(const void* p) {
    uint32_t a;
    asm("{ .reg .u64 t; cvta.to.shared.u64 t, %1; cvt.u32.u64 %0, t; }"
        : "=r"(a) : "l"(p));
    return a;
}

__device__ __forceinline__ void cp_async16(uint32_t smem_addr, const void* gptr) {
    asm volatile("cp.async.cg.shared.global [%0], [%1], 16;"
                 :: "r"(smem_addr),
                    "l"((unsigned long long)__cvta_generic_to_global(gptr))
                 : "memory");
}
#define CP_COMMIT() asm volatile("cp.async.commit_group;" ::: "memory")
#define CP_WAIT(n)  asm volatile("cp.async.wait_group %0;" :: "n"(n) : "memory")

#define LDSM4(r, addr)                                                         \
    asm volatile("ldmatrix.sync.aligned.m8n8.x4.shared.b16 {%0,%1,%2,%3}, [%4];" \
                 : "=r"((r)[0]), "=r"((r)[1]), "=r"((r)[2]), "=r"((r)[3])      \
                 : "r"(addr))

// m16n8k16 fp16 MMA, fp32 accumulate.
#define MMA_F16(d, a, b0, b1)                                                  \
    asm volatile(                                                              \
        "mma.sync.aligned.m16n8k16.row.col.f32.f16.f16.f32 "                   \
        "{%0,%1,%2,%3}, {%4,%5,%6,%7}, {%8,%9}, {%0,%1,%2,%3};"                \
        : "+f"((d)[0]), "+f"((d)[1]), "+f"((d)[2]), "+f"((d)[3])               \
        : "r"((a)[0]), "r"((a)[1]), "r"((a)[2]), "r"((a)[3]),                  \
          "r"(b0), "r"(b1))

// ---------------------------------------------------------------------------
// ONE fused prep kernel (R14 gather structure; inv_perm folded in as block 0).
// Block 0:                      build g_inv (scatter), release flag.
// Blocks [1, 1+XBLOCKS):        x conversion (no dependency on g_inv).
// Blocks [1+XBLOCKS, ..+OUT_F): W dequant (acquire flag, gather via g_inv).
// W blocks launch ~30us of x-work after block 0 retires, so the flag wait
// virtually never spins. Replays rewrite identical g_inv values -> benign.
// ---------------------------------------------------------------------------
#define XBLOCKS (TOKENS * IN_F / 4 / 1024)       // 8192

__global__ void __launch_bounds__(256)
prep_kernel(const float4* __restrict__ x, const int* __restrict__ wp,
            const float* __restrict__ ws, const int* __restrict__ perm) {
    const int bid = blockIdx.x;
    const int tid = threadIdx.x;
    if (bid == 0) {
        // --- inverse permutation ---
        for (int j = tid; j < IN_F; j += 256) g_inv[perm[j]] = j;
        __threadfence();
        __syncthreads();
        if (tid == 0) atomicExch(&g_inv_ready, 1);   // release
    } else if (bid <= XBLOCKS) {
        // --- x path: fp32 -> fp16, 4 float4 per thread ---
        const int xb = bid - 1;                  // 0..XBLOCKS-1
        const float4* src = x + (size_t)xb * 1024;
        uint2* dst = reinterpret_cast<uint2*>(g_x) + (size_t)xb * 1024;
        #pragma unroll
        for (int it = 0; it < 4; ++it) {
            int i = tid + it * 256;
            float4 v = src[i];
            __half2 h0 = __floats2half2_rn(v.x, v.y);
            __half2 h1 = __floats2half2_rn(v.z, v.w);
            uint2 packed;
            packed.x = *reinterpret_cast<uint32_t*>(&h0);
            packed.y = *reinterpret_cast<uint32_t*>(&h1);
            dst[i] = packed;
        }
    } else {
        // --- W path: dequant + perm-fold (gather via g_inv), fp16 ---
        const int o = bid - 1 - XBLOCKS;         // 0..OUT_F-1
        if (tid == 0) {                          // acquire g_inv
            while (atomicAdd(&g_inv_ready, 0) == 0) __nanosleep(64);
        }
        __syncthreads();
        __threadfence();
        __shared__ int   srow[IN_F / 2];
        __shared__ float sscale[IN_F / GS];
        for (int i = tid; i < IN_F / 2; i += 256)
            srow[i] = wp[(size_t)o * (IN_F / 2) + i];
        if (tid < IN_F / GS) sscale[tid] = ws[(size_t)o * (IN_F / GS) + tid];
        __syncthreads();
        for (int k = tid; k < IN_F; k += 256) {
            int j = g_inv[k];                    // source (pre-perm) column
            int b = srow[j >> 1];
            int q = (((j & 1) ? (b >> 4) : b) & 0xF) - 8;
            float w = (float)q * sscale[j >> 7]; // group = j / 128
            g_w[(size_t)o * IN_F + k] = __float2half_rn(w);
        }
    }
}

// ---------------------------------------------------------------------------
// GEMM (R13/R14 version, measured 582.0us three times -- DO NOT TOUCH):
// 128x128 CTA tile, 3-stage cp.async pipeline, m16n8k16 fp16 MMA, ldmatrix.x4
// fragment loads; refill split into two halves (post-barrier and mid-chunk).
// Warp grid 4(M) x 2(N); warp tile 32x64. 2 CTAs/SM.
// smem rows 128B; swizzle: (seg*16) ^ ((row&7)<<4).
// ---------------------------------------------------------------------------
__device__ __forceinline__ void load_stage_half(uint32_t sbase, int s, int chunk,
                                                int m0, int n0, int tid, int half) {
    uint32_t st = sbase + (uint32_t)s * STAGE_BYTES;
    const __half* gA = g_x + (size_t)m0 * IN_F + chunk * BK;
    const __half* gB = g_w + (size_t)n0 * IN_F + chunk * BK;
    #pragma unroll
    for (int it = half * 2; it < half * 2 + 2; ++it) {
        int u = tid + it * 256;                  // 0..1023
        int r = u >> 3, seg = u & 7;             // row, 16B-seg within 128B row
        uint32_t so = (uint32_t)(r * 128) + (uint32_t)((seg * 16) ^ ((r & 7) << 4));
        cp_async16(st + so,         gA + (size_t)r * IN_F + seg * 8);
        cp_async16(st + OFF_B + so, gB + (size_t)r * IN_F + seg * 8);
    }
}

__global__ void __launch_bounds__(256, 2)
gemm_kernel(const float* __restrict__ bias, float* __restrict__ out) {
    extern __shared__ char smem[];
    const uint32_t sbase = smem_u32(smem);
    const int tid  = threadIdx.x;
    const int wid  = tid >> 5;
    const int lane = tid & 31;
    const int bid  = blockIdx.x;
    const int n0 = (bid & (GRID_N - 1)) * BN;    // n-fast: W slab stays in L2
    const int m0 = (bid / GRID_N) * BM;

    const int wm = wid >> 1;                     // 0..3
    const int wn = wid & 1;                      // 0..1
    const int g  = lane >> 2;                    // 0..7
    const int t  = lane & 3;                     // 0..3

    // ldmatrix lane roles
    const int mtx = lane >> 3;                   // matrix index 0..3
    const int rr  = lane & 7;                    // row within matrix
    const uint32_t swz = (uint32_t)rr << 4;      // XOR swizzle for this row

    // A: matrix m -> rows (wm*32 + mi*16 + (m&1)*8 + rr), k-half (m>>1)
    const uint32_t aRowOff = (uint32_t)((wm * 32 + (mtx & 1) * 8 + rr) * 128);
    const uint32_t kbA = (uint32_t)((mtx >> 1) * 16);
    // B: matrix m -> rows (wn*64 + jp*16 + (m>>1)*8 + rr), k-half (m&1)
    const uint32_t bRowOff = (uint32_t)((wn * 64 + (mtx >> 1) * 8 + rr) * 128) + OFF_B;
    const uint32_t kbB = (uint32_t)((mtx & 1) * 16);

    float acc[2][8][4];
    #pragma unroll
    for (int i = 0; i < 2; ++i)
        #pragma unroll
        for (int j = 0; j < 8; ++j)
            #pragma unroll
            for (int c = 0; c < 4; ++c) acc[i][j][c] = 0.0f;

    #pragma unroll
    for (int c = 0; c < STAGES - 1; ++c) {
        load_stage_half(sbase, c, c, m0, n0, tid, 0);
        load_stage_half(sbase, c, c, m0, n0, tid, 1);
        CP_COMMIT();
    }

    int s_cons = 0, s_prod = STAGES - 1;

    #pragma unroll 1
    for (int i = 0; i < NCHUNK; ++i) {
        CP_WAIT(STAGES - 2);                     // chunk i resident
        __syncthreads();
        const bool refill = (i + STAGES - 1 < NCHUNK);
        if (refill) load_stage_half(sbase, s_prod, i + STAGES - 1, m0, n0, tid, 0);

        const uint32_t st = sbase + (uint32_t)s_cons * STAGE_BYTES;
        if (++s_cons == STAGES) s_cons = 0;

        #pragma unroll
        for (int ks = 0; ks < 4; ++ks) {         // k16 steps; 32B per step
            if (ks == 2) {                       // second refill half + commit
                if (refill) {
                    load_stage_half(sbase, s_prod, i + STAGES - 1, m0, n0, tid, 1);
                    if (++s_prod == STAGES) s_prod = 0;
                }
                CP_COMMIT();
            }
            const uint32_t colA = ((uint32_t)(ks * 32) + kbA) ^ swz;
            const uint32_t colB = ((uint32_t)(ks * 32) + kbB) ^ swz;
            uint32_t ar[2][4];
            LDSM4(ar[0], st + aRowOff + colA);              // mi=0 (rows +0)
            LDSM4(ar[1], st + aRowOff + 16 * 128 + colA);   // mi=1 (rows +16)
            #pragma unroll
            for (int jp = 0; jp < 4; ++jp) {     // regs 0,1 = j even; 2,3 = j odd
                uint32_t bq[4];
                LDSM4(bq, st + bRowOff + (uint32_t)(jp * 16 * 128) + colB);
                MMA_F16(acc[0][jp * 2],     ar[0], bq[0], bq[1]);
                MMA_F16(acc[1][jp * 2],     ar[1], bq[0], bq[1]);
                MMA_F16(acc[0][jp * 2 + 1], ar[0], bq[2], bq[3]);
                MMA_F16(acc[1][jp * 2 + 1], ar[1], bq[2], bq[3]);
            }
        }
    }

    // Epilogue: c0/c1 at (row, 2t), c2/c3 at (row+8, 2t); add bias, float2 stores
    #pragma unroll
    for (int mi = 0; mi < 2; ++mi) {
        const int row0 = m0 + wm * 32 + mi * 16 + g;
        #pragma unroll
        for (int j = 0; j < 8; ++j) {
            const int col = n0 + wn * 64 + j * 8 + t * 2;
            const float2 b2 = *reinterpret_cast<const float2*>(bias + col);
            float2 v0, v1;
            v0.x = acc[mi][j][0] + b2.x;  v0.y = acc[mi][j][1] + b2.y;
            v1.x = acc[mi][j][2] + b2.x;  v1.y = acc[mi][j][3] + b2.y;
            *reinterpret_cast<float2*>(out + (size_t)row0 * OUT_F + col) = v0;
            *reinterpret_cast<float2*>(out + (size_t)(row0 + 8) * OUT_F + col) = v1;
        }
    }
}

// ---------------------------------------------------------------------------
// Launch
// ---------------------------------------------------------------------------
extern "C" void kernel_launch(void* const* d_in, const int* in_sizes, int n_in,
                              void* d_out, int out_size) {
    const float* x    = (const float*)d_in[0];
    const int*   wp   = (const int*)d_in[1];
    const float* ws   = (const float*)d_in[2];
    const int*   perm = (const int*)d_in[3];
    const float* bias = (const float*)d_in[4];
    float* out = (float*)d_out;

    prep_kernel<<<1 + XBLOCKS + OUT_F, 256>>>((const float4*)x, wp, ws, perm);

    cudaFuncSetAttribute(gemm_kernel, cudaFuncAttributeMaxDynamicSharedMemorySize,
                         GEMM_SMEM);
    gemm_kernel<<<GRID_M * GRID_N, 256, GEMM_SMEM>>>(bias, out);
}

// round 17
// speedup vs baseline: 1.0223x; 1.0102x over previous
#include <cuda_runtime.h>
#include <cuda_fp16.h>
#include <cstdint>
#include <cstddef>

// ---------------------------------------------------------------------------
// Problem constants
// ---------------------------------------------------------------------------
#define TOKENS   8192
#define IN_F     4096
#define OUT_F    4096
#define GS       128

// GEMM tiling (fp16): BK = 64 halves = 128B rows
#define BM 128
#define BN 128
#define BK 64
#define STAGES 3                      // 96KB smem -> 2 CTAs/SM
#define NCHUNK (IN_F / BK)            // 64
#define GRID_N (OUT_F / BN)           // 32
#define GRID_M (TOKENS / BM)          // 64

#define OFF_B       (BM * BK * 2)     // 16384 (A tile bytes)
#define STAGE_BYTES ((BM + BN) * BK * 2)   // 32768
#define GEMM_SMEM   (STAGES * STAGE_BYTES) // 98304

// ---------------------------------------------------------------------------
// Device scratch (static -- no cudaMalloc anywhere)
// ---------------------------------------------------------------------------
__device__ __half g_x[(size_t)TOKENS * IN_F];   // x rounded to fp16
__device__ __half g_w[(size_t)OUT_F * IN_F];    // dequant + perm-folded fp16
__device__ int    g_inv[IN_F];

// ---------------------------------------------------------------------------
// PTX helpers (family-common: mma.sync / ldmatrix / cp.async)
// ---------------------------------------------------------------------------
__device__ __forceinline__ uint32_t smem_u32(const void* p) {
    uint32_t a;
    asm("{ .reg .u64 t; cvta.to.shared.u64 t, %1; cvt.u32.u64 %0, t; }"
        : "=r"(a) : "l"(p));
    return a;
}

__device__ __forceinline__ void cp_async16(uint32_t smem_addr, const void* gptr) {
    asm volatile("cp.async.cg.shared.global [%0], [%1], 16;"
                 :: "r"(smem_addr),
                    "l"((unsigned long long)__cvta_generic_to_global(gptr))
                 : "memory");
}
#define CP_COMMIT() asm volatile("cp.async.commit_group;" ::: "memory")
#define CP_WAIT(n)  asm volatile("cp.async.wait_group %0;" :: "n"(n) : "memory")

#define LDSM4(r, addr)                                                         \
    asm volatile("ldmatrix.sync.aligned.m8n8.x4.shared.b16 {%0,%1,%2,%3}, [%4];" \
                 : "=r"((r)[0]), "=r"((r)[1]), "=r"((r)[2]), "=r"((r)[3])      \
                 : "r"(addr))

// m16n8k16 fp16 MMA, fp32 accumulate.
#define MMA_F16(d, a, b0, b1)                                                  \
    asm volatile(                                                              \
        "mma.sync.aligned.m16n8k16.row.col.f32.f16.f16.f32 "                   \
        "{%0,%1,%2,%3}, {%4,%5,%6,%7}, {%8,%9}, {%0,%1,%2,%3};"                \
        : "+f"((d)[0]), "+f"((d)[1]), "+f"((d)[2]), "+f"((d)[3])               \
        : "r"((a)[0]), "r"((a)[1]), "r"((a)[2]), "r"((a)[3]),                  \
          "r"(b0), "r"(b1))

// ---------------------------------------------------------------------------
// Prep (R14 structure, measured 57.5us): tiny inverse-perm kernel, then ONE
// fused kernel whose block ranges cover W dequant (gather via g_inv) and the
// x conversion so the two streams run concurrently. x reads use evict-first
// (__ldcs): the fp32 input is single-use and must not churn L2.
// ---------------------------------------------------------------------------
__global__ void inv_perm_kernel(const int* __restrict__ perm) {
    int j = blockIdx.x * blockDim.x + threadIdx.x;
    if (j < IN_F) g_inv[perm[j]] = j;
}

#define XBLOCKS (TOKENS * IN_F / 4 / 1024)       // 8192 (1024 float4 per block)

__global__ void __launch_bounds__(256)
prep_kernel(const float4* __restrict__ x, const int* __restrict__ wp,
            const float* __restrict__ ws) {
    const int bid = blockIdx.x;
    const int tid = threadIdx.x;
    if (bid < OUT_F) {
        // --- W path: dequant + perm-fold (gather), fp16 ---
        __shared__ int   srow[IN_F / 2];
        __shared__ float sscale[IN_F / GS];
        for (int i = tid; i < IN_F / 2; i += 256)
            srow[i] = wp[(size_t)bid * (IN_F / 2) + i];
        if (tid < IN_F / GS) sscale[tid] = ws[(size_t)bid * (IN_F / GS) + tid];
        __syncthreads();
        for (int k = tid; k < IN_F; k += 256) {
            int j = g_inv[k];                    // source (pre-perm) column
            int b = srow[j >> 1];
            int q = (((j & 1) ? (b >> 4) : b) & 0xF) - 8;
            float w = (float)q * sscale[j >> 7]; // group = j / 128
            g_w[(size_t)bid * IN_F + k] = __float2half_rn(w);
        }
    } else {
        // --- x path: fp32 -> fp16, 4 float4 per thread, evict-first reads ---
        const int xb = bid - OUT_F;              // 0..XBLOCKS-1
        const float4* src = x + (size_t)xb * 1024;
        uint2* dst = reinterpret_cast<uint2*>(g_x) + (size_t)xb * 1024;
        #pragma unroll
        for (int it = 0; it < 4; ++it) {
            int i = tid + it * 256;
            float4 v = __ldcs(src + i);          // single-use stream
            __half2 h0 = __floats2half2_rn(v.x, v.y);
            __half2 h1 = __floats2half2_rn(v.z, v.w);
            uint2 packed;
            packed.x = *reinterpret_cast<uint32_t*>(&h0);
            packed.y = *reinterpret_cast<uint32_t*>(&h1);
            dst[i] = packed;
        }
    }
}

// ---------------------------------------------------------------------------
// GEMM (R13/R14 mainloop, measured 582.0us -- structure untouched): 128x128
// CTA tile, 3-stage cp.async pipeline, m16n8k16 fp16 MMA, ldmatrix.x4
// fragment loads; refill split into two halves (post-barrier and mid-chunk).
// Warp grid 4(M) x 2(N); warp tile 32x64. 2 CTAs/SM.
// smem rows 128B; swizzle: (seg*16) ^ ((row&7)<<4).
// Epilogue stores use __stcs (write-once output; keep W slab L2-resident).
// ---------------------------------------------------------------------------
__device__ __forceinline__ void load_stage_half(uint32_t sbase, int s, int chunk,
                                                int m0, int n0, int tid, int half) {
    uint32_t st = sbase + (uint32_t)s * STAGE_BYTES;
    const __half* gA = g_x + (size_t)m0 * IN_F + chunk * BK;
    const __half* gB = g_w + (size_t)n0 * IN_F + chunk * BK;
    #pragma unroll
    for (int it = half * 2; it < half * 2 + 2; ++it) {
        int u = tid + it * 256;                  // 0..1023
        int r = u >> 3, seg = u & 7;             // row, 16B-seg within 128B row
        uint32_t so = (uint32_t)(r * 128) + (uint32_t)((seg * 16) ^ ((r & 7) << 4));
        cp_async16(st + so,         gA + (size_t)r * IN_F + seg * 8);
        cp_async16(st + OFF_B + so, gB + (size_t)r * IN_F + seg * 8);
    }
}

__global__ void __launch_bounds__(256, 2)
gemm_kernel(const float* __restrict__ bias, float* __restrict__ out) {
    extern __shared__ char smem[];
    const uint32_t sbase = smem_u32(smem);
    const int tid  = threadIdx.x;
    const int wid  = tid >> 5;
    const int lane = tid & 31;
    const int bid  = blockIdx.x;
    const int n0 = (bid & (GRID_N - 1)) * BN;    // n-fast: W slab stays in L2
    const int m0 = (bid / GRID_N) * BM;

    const int wm = wid >> 1;                     // 0..3
    const int wn = wid & 1;                      // 0..1
    const int g  = lane >> 2;                    // 0..7
    const int t  = lane & 3;                     // 0..3

    // ldmatrix lane roles
    const int mtx = lane >> 3;                   // matrix index 0..3
    const int rr  = lane & 7;                    // row within matrix
    const uint32_t swz = (uint32_t)rr << 4;      // XOR swizzle for this row

    // A: matrix m -> rows (wm*32 + mi*16 + (m&1)*8 + rr), k-half (m>>1)
    const uint32_t aRowOff = (uint32_t)((wm * 32 + (mtx & 1) * 8 + rr) * 128);
    const uint32_t kbA = (uint32_t)((mtx >> 1) * 16);
    // B: matrix m -> rows (wn*64 + jp*16 + (m>>1)*8 + rr), k-half (m&1)
    const uint32_t bRowOff = (uint32_t)((wn * 64 + (mtx >> 1) * 8 + rr) * 128) + OFF_B;
    const uint32_t kbB = (uint32_t)((mtx & 1) * 16);

    float acc[2][8][4];
    #pragma unroll
    for (int i = 0; i < 2; ++i)
        #pragma unroll
        for (int j = 0; j < 8; ++j)
            #pragma unroll
            for (int c = 0; c < 4; ++c) acc[i][j][c] = 0.0f;

    #pragma unroll
    for (int c = 0; c < STAGES - 1; ++c) {
        load_stage_half(sbase, c, c, m0, n0, tid, 0);
        load_stage_half(sbase, c, c, m0, n0, tid, 1);
        CP_COMMIT();
    }

    int s_cons = 0, s_prod = STAGES - 1;

    #pragma unroll 1
    for (int i = 0; i < NCHUNK; ++i) {
        CP_WAIT(STAGES - 2);                     // chunk i resident
        __syncthreads();
        const bool refill = (i + STAGES - 1 < NCHUNK);
        if (refill) load_stage_half(sbase, s_prod, i + STAGES - 1, m0, n0, tid, 0);

        const uint32_t st = sbase + (uint32_t)s_cons * STAGE_BYTES;
        if (++s_cons == STAGES) s_cons = 0;

        #pragma unroll
        for (int ks = 0; ks < 4; ++ks) {         // k16 steps; 32B per step
            if (ks == 2) {                       // second refill half + commit
                if (refill) {
                    load_stage_half(sbase, s_prod, i + STAGES - 1, m0, n0, tid, 1);
                    if (++s_prod == STAGES) s_prod = 0;
                }
                CP_COMMIT();
            }
            const uint32_t colA = ((uint32_t)(ks * 32) + kbA) ^ swz;
            const uint32_t colB = ((uint32_t)(ks * 32) + kbB) ^ swz;
            uint32_t ar[2][4];
            LDSM4(ar[0], st + aRowOff + colA);              // mi=0 (rows +0)
            LDSM4(ar[1], st + aRowOff + 16 * 128 + colA);   // mi=1 (rows +16)
            #pragma unroll
            for (int jp = 0; jp < 4; ++jp) {     // regs 0,1 = j even; 2,3 = j odd
                uint32_t bq[4];
                LDSM4(bq, st + bRowOff + (uint32_t)(jp * 16 * 128) + colB);
                MMA_F16(acc[0][jp * 2],     ar[0], bq[0], bq[1]);
                MMA_F16(acc[1][jp * 2],     ar[1], bq[0], bq[1]);
                MMA_F16(acc[0][jp * 2 + 1], ar[0], bq[2], bq[3]);
                MMA_F16(acc[1][jp * 2 + 1], ar[1], bq[2], bq[3]);
            }
        }
    }

    // Epilogue: c0/c1 at (row, 2t), c2/c3 at (row+8, 2t); add bias;
    // evict-first (write-once) float2 stores.
    #pragma unroll
    for (int mi = 0; mi < 2; ++mi) {
        const int row0 = m0 + wm * 32 + mi * 16 + g;
        #pragma unroll
        for (int j = 0; j < 8; ++j) {
            const int col = n0 + wn * 64 + j * 8 + t * 2;
            const float2 b2 = *reinterpret_cast<const float2*>(bias + col);
            float2 v0, v1;
            v0.x = acc[mi][j][0] + b2.x;  v0.y = acc[mi][j][1] + b2.y;
            v1.x = acc[mi][j][2] + b2.x;  v1.y = acc[mi][j][3] + b2.y;
            __stcs(reinterpret_cast<float2*>(out + (size_t)row0 * OUT_F + col), v0);
            __stcs(reinterpret_cast<float2*>(out + (size_t)(row0 + 8) * OUT_F + col), v1);
        }
    }
}

// ---------------------------------------------------------------------------
// Launch
// ---------------------------------------------------------------------------
extern "C" void kernel_launch(void* const* d_in, const int* in_sizes, int n_in,
                              void* d_out, int out_size) {
    const float* x    = (const float*)d_in[0];
    const int*   wp   = (const int*)d_in[1];
    const float* ws   = (const float*)d_in[2];
    const int*   perm = (const int*)d_in[3];
    const float* bias = (const float*)d_in[4];
    float* out = (float*)d_out;

    inv_perm_kernel<<<IN_F / 256, 256>>>(perm);
    prep_kernel<<<OUT_F + XBLOCKS, 256>>>((const float4*)x, wp, ws);

    cudaFuncSetAttribute(gemm_kernel, cudaFuncAttributeMaxDynamicSharedMemorySize,
                         GEMM_SMEM);
    gemm_kernel<<<GRID_M * GRID_N, 256, GEMM_SMEM>>>(bias, out);
}